// round 5
// baseline (speedup 1.0000x reference)
#include <cuda_runtime.h>
#include <cuda_bf16.h>
#include <cstdint>

#define NN 20000
#define SS 4096
#define EE 640000
#define DD 256
#define M_PAD 20096   // 157 * 128

// ---------------- scratch (zero-initialized device globals) ----------------
__device__ float g_h[M_PAD * DD];          // current node features (tf32-rounded)
__device__ float g_tmp[M_PAD * DD];        // h @ W
__device__ float g_wt[DD * DD];            // W^T (K-major), tf32-rounded
__device__ int   g_cnt[NN];
__device__ int   g_off[NN + 1];
__device__ int   g_cur[NN];
__device__ int2  g_edge[EE];               // packed (src_row, attr_bits), CSR order

// ---------------- helpers ----------------
__device__ __forceinline__ uint32_t smem_u32(const void* p) {
    uint32_t a;
    asm("{ .reg .u64 t; cvta.to.shared.u64 t, %1; cvt.u32.u64 %0, t; }" : "=r"(a) : "l"(p));
    return a;
}
__device__ __forceinline__ float to_tf32(float x) {
    uint32_t u;
    asm("cvt.rna.tf32.f32 %0, %1;" : "=r"(u) : "f"(x));
    return __uint_as_float(u);
}
#define CP_ASYNC16(s, g) asm volatile("cp.async.cg.shared.global [%0], [%1], 16;" :: "r"(s), "l"(g) : "memory")
#define CP_COMMIT()      asm volatile("cp.async.commit_group;" ::: "memory")
#define CP_WAIT(n)       asm volatile("cp.async.wait_group %0;" :: "n"(n) : "memory")

__device__ __forceinline__ void mma_tf32(float* d, const uint32_t* a, const uint32_t* b) {
    asm volatile(
        "mma.sync.aligned.m16n8k8.row.col.f32.tf32.tf32.f32 "
        "{%0,%1,%2,%3}, {%4,%5,%6,%7}, {%8,%9}, {%0,%1,%2,%3};"
        : "+f"(d[0]), "+f"(d[1]), "+f"(d[2]), "+f"(d[3])
        : "r"(a[0]), "r"(a[1]), "r"(a[2]), "r"(a[3]), "r"(b[0]), "r"(b[1]));
}

// =====================================================================
// Row embedding: rank-16 factorization, direct divergent accumulate (R2 style)
// =====================================================================
__device__ __forceinline__ void accum16(float* acc, float jf,
                                        const float* w1s, const float* b1s) {
#pragma unroll
    for (int k = 0; k < 16; k++)
        acc[k] += fmaxf(fmaf(jf, w1s[k], b1s[k]), 0.0f);
}

__global__ __launch_bounds__(256) void row_embed_kernel(
        const float* __restrict__ init,
        const float* __restrict__ w1, const float* __restrict__ b1,
        const float* __restrict__ w2, const float* __restrict__ b2) {
    __shared__ float s_part[256][17];
    __shared__ float s_p2[16][17];
    __shared__ float s_fin[16];
    __shared__ int   s_cnt;
    __shared__ float s_w1[16], s_b1[16];
    const int row = blockIdx.x;
    const int tid = threadIdx.x;
    if (tid == 0) s_cnt = 0;
    if (tid < 16) { s_w1[tid] = w1[tid]; s_b1[tid] = b1[tid]; }
    __syncthreads();

    float acc[16];
#pragma unroll
    for (int k = 0; k < 16; k++) acc[k] = 0.0f;
    int cnt = 0;

    const float4* rp = (const float4*)(init + (size_t)row * SS);
#pragma unroll
    for (int it = 0; it < 4; it++) {
        int fi = it * 256 + tid;
        float4 v = rp[fi];
        int j = fi * 4;
        if (v.x != 0.0f) { cnt++; accum16(acc, (float)(j + 0), s_w1, s_b1); }
        if (v.y != 0.0f) { cnt++; accum16(acc, (float)(j + 1), s_w1, s_b1); }
        if (v.z != 0.0f) { cnt++; accum16(acc, (float)(j + 2), s_w1, s_b1); }
        if (v.w != 0.0f) { cnt++; accum16(acc, (float)(j + 3), s_w1, s_b1); }
    }
    if (cnt) atomicAdd(&s_cnt, cnt);
#pragma unroll
    for (int k = 0; k < 16; k++) s_part[tid][k] = acc[k];
    __syncthreads();

    {
        const int k16 = tid & 15, grp = tid >> 4;
        float p = 0.0f;
#pragma unroll
        for (int r = 0; r < 16; r++) p += s_part[grp * 16 + r][k16];
        s_p2[grp][k16] = p;
    }
    __syncthreads();
    if (tid < 16) {
        float f = 0.0f;
#pragma unroll
        for (int g2 = 0; g2 < 16; g2++) f += s_p2[g2][tid];
        s_fin[tid] = f;
    }
    __syncthreads();

    const float cntf = (float)s_cnt;
    float val = cntf * b2[tid];
#pragma unroll
    for (int k = 0; k < 16; k++) val = fmaf(s_fin[k], w2[k * DD + tid], val);
    g_h[(size_t)row * DD + tid] = to_tf32(val / fmaxf(cntf, 1.0f));
}

// ---------------- CSR build ----------------
__global__ void zero_counts_kernel() {
    int i = blockIdx.x * blockDim.x + threadIdx.x;
    if (i < NN) g_cnt[i] = 0;
}

__global__ void count_kernel(const int* __restrict__ col) {
    int e = blockIdx.x * blockDim.x + threadIdx.x;
    if (e < EE) atomicAdd(&g_cnt[col[e]], 1);
}

__global__ void scan_kernel() {
    __shared__ int s_w[32];
    __shared__ int s_carry;
    const int tid = threadIdx.x, lane = tid & 31, wid = tid >> 5;
    if (tid == 0) s_carry = 0;
    __syncthreads();
    for (int base = 0; base < NN; base += 1024) {
        int i = base + tid;
        int v = (i < NN) ? g_cnt[i] : 0;
        int x = v;
#pragma unroll
        for (int off = 1; off < 32; off <<= 1) {
            int t = __shfl_up_sync(0xffffffffu, x, off);
            if (lane >= off) x += t;
        }
        if (lane == 31) s_w[wid] = x;
        __syncthreads();
        if (tid < 32) {
            int y = s_w[tid];
#pragma unroll
            for (int off = 1; off < 32; off <<= 1) {
                int t = __shfl_up_sync(0xffffffffu, y, off);
                if (lane >= off) y += t;
            }
            s_w[tid] = y;
        }
        __syncthreads();
        int carry = s_carry;
        int pre = (wid > 0) ? s_w[wid - 1] : 0;
        int excl = carry + pre + x - v;
        if (i < NN) { g_off[i] = excl; g_cur[i] = excl; }
        __syncthreads();
        if (tid == 0) s_carry = carry + s_w[31];
        __syncthreads();
    }
    if (tid == 0) g_off[NN] = s_carry;
}

__global__ void scatter_kernel(const int* __restrict__ row, const int* __restrict__ col,
                               const float* __restrict__ attr) {
    int e = blockIdx.x * blockDim.x + threadIdx.x;
    if (e >= EE) return;
    int c = col[e];
    int p = atomicAdd(&g_cur[c], 1);
    g_edge[p] = make_int2(row[e], __float_as_int(attr[e]));
}

// ---------------- W transpose (tf32-rounded): g_wt[n][k] = W[k][n] ----------------
__global__ void transpose_w_kernel(const float* __restrict__ W) {
    __shared__ float t[32][33];
    const int bx = blockIdx.x & 7;
    const int by = blockIdx.x >> 3;
    const int lx = threadIdx.x & 31, ly = threadIdx.x >> 5;
#pragma unroll
    for (int r = 0; r < 4; r++)
        t[ly + r * 8][lx] = to_tf32(W[(bx * 32 + ly + r * 8) * DD + by * 32 + lx]);
    __syncthreads();
#pragma unroll
    for (int r = 0; r < 4; r++)
        g_wt[(by * 32 + ly + r * 8) * DD + bx * 32 + lx] = t[lx][ly + r * 8];
}

// =====================================================================
// tf32 mma.sync GEMM, cp.async double-buffered (BM=BN=128, BK=32)
// =====================================================================
#define ASTR 36
#define TILE_F (128 * ASTR)
#define BUF_BYTES (2 * TILE_F * 4)
#define SMEM_GEMM_TOTAL (2 * BUF_BYTES)     // 73728

__global__ __launch_bounds__(256, 2) void mma_gemm_kernel() {
    extern __shared__ float smem[];
    const int tid = threadIdx.x;
    const int lane = tid & 31;
    const int wid = tid >> 5;
    const int g = lane >> 2, t = lane & 3;
    const int wm = (wid & 1) * 64;
    const int wn = (wid >> 1) * 32;
    const int bn = blockIdx.x * 128;
    const int bm = blockIdx.y * 128;

    const uint32_t sbase = smem_u32(smem);
    const float* Ab = g_h + (size_t)bm * DD;
    const float* Bb = g_wt + (size_t)bn * DD;

    float acc[4][4][4];
#pragma unroll
    for (int i = 0; i < 4; i++)
#pragma unroll
        for (int j = 0; j < 4; j++)
#pragma unroll
            for (int c = 0; c < 4; c++) acc[i][j][c] = 0.0f;

    auto issue = [&](int c, int buf) {
        const uint32_t sa = sbase + buf * BUF_BYTES;
        const uint32_t sb = sa + TILE_F * 4;
        const int k0 = c * 32;
#pragma unroll
        for (int i = 0; i < 4; i++) {
            int task = tid + i * 256;
            int r = task >> 3, q = task & 7;
            CP_ASYNC16(sa + (uint32_t)(r * ASTR + q * 4) * 4,
                       (const char*)(Ab + (size_t)r * DD + k0 + q * 4));
        }
#pragma unroll
        for (int i = 0; i < 4; i++) {
            int task = tid + i * 256;
            int r = task >> 3, q = task & 7;
            CP_ASYNC16(sb + (uint32_t)(r * ASTR + q * 4) * 4,
                       (const char*)(Bb + (size_t)r * DD + k0 + q * 4));
        }
        CP_COMMIT();
    };

    issue(0, 0);

    for (int c = 0; c < 8; c++) {
        __syncthreads();
        if (c < 7) issue(c + 1, (c + 1) & 1);
        if (c < 7) { CP_WAIT(1); } else { CP_WAIT(0); }
        __syncthreads();

        const float* Asp = smem + (c & 1) * (BUF_BYTES / 4);
        const float* Bsp = Asp + TILE_F;
#pragma unroll
        for (int ks = 0; ks < 4; ks++) {
            const int kb = ks * 8;
            uint32_t bf[4][2];
#pragma unroll
            for (int nt = 0; nt < 4; nt++) {
                const float* bp = Bsp + (wn + nt * 8 + g) * ASTR + kb + t;
                bf[nt][0] = __float_as_uint(bp[0]);
                bf[nt][1] = __float_as_uint(bp[4]);
            }
#pragma unroll
            for (int mt = 0; mt < 4; mt++) {
                const int m0 = wm + mt * 16;
                const float* ap0 = Asp + (m0 + g) * ASTR + kb + t;
                const float* ap1 = Asp + (m0 + g + 8) * ASTR + kb + t;
                uint32_t af[4];
                af[0] = __float_as_uint(ap0[0]);
                af[1] = __float_as_uint(ap1[0]);
                af[2] = __float_as_uint(ap0[4]);
                af[3] = __float_as_uint(ap1[4]);
#pragma unroll
                for (int nt = 0; nt < 4; nt++)
                    mma_tf32(acc[mt][nt], af, bf[nt]);
            }
        }
    }

#pragma unroll
    for (int mt = 0; mt < 4; mt++) {
#pragma unroll
        for (int nt = 0; nt < 4; nt++) {
            const int r0 = bm + wm + mt * 16 + g;
            const int c0 = bn + wn + nt * 8 + 2 * t;
            *(float2*)(g_tmp + (size_t)r0 * DD + c0) =
                make_float2(acc[mt][nt][0], acc[mt][nt][1]);
            *(float2*)(g_tmp + (size_t)(r0 + 8) * DD + c0) =
                make_float2(acc[mt][nt][2], acc[mt][nt][3]);
        }
    }
}

// ---------------- h_next[c] = relu( sum_{e: col=c} attr_e * g_tmp[row_e] ) ----------------
__global__ __launch_bounds__(256) void agg_kernel(float* __restrict__ dst_out) {
    const int c = blockIdx.x;
    const int tid = threadIdx.x;
    const int rs = g_off[c], re = g_off[c + 1];
    float acc = 0.0f;
    int e = rs;
    for (; e + 4 <= re; e += 4) {
        int2 e0 = g_edge[e],     e1 = g_edge[e + 1];
        int2 e2 = g_edge[e + 2], e3 = g_edge[e + 3];
        float v0 = g_tmp[(size_t)e0.x * DD + tid];
        float v1 = g_tmp[(size_t)e1.x * DD + tid];
        float v2 = g_tmp[(size_t)e2.x * DD + tid];
        float v3 = g_tmp[(size_t)e3.x * DD + tid];
        acc = fmaf(__int_as_float(e0.y), v0, acc);
        acc = fmaf(__int_as_float(e1.y), v1, acc);
        acc = fmaf(__int_as_float(e2.y), v2, acc);
        acc = fmaf(__int_as_float(e3.y), v3, acc);
    }
    for (; e < re; e++) {
        int2 ee = g_edge[e];
        acc = fmaf(__int_as_float(ee.y), g_tmp[(size_t)ee.x * DD + tid], acc);
    }
    float r = fmaxf(acc, 0.0f);
    if (dst_out) dst_out[(size_t)c * DD + tid] = r;
    else         g_h[(size_t)c * DD + tid] = to_tf32(r);
}

// ---------------- launch ----------------
extern "C" void kernel_launch(void* const* d_in, const int* in_sizes, int n_in,
                              void* d_out, int out_size) {
    const float* init = (const float*)d_in[0];
    const int*   ei   = (const int*)d_in[1];
    const float* attr = (const float*)d_in[2];
    const float* w1   = (const float*)d_in[3];
    const float* b1   = (const float*)d_in[4];
    const float* w2   = (const float*)d_in[5];
    const float* b2   = (const float*)d_in[6];
    const float* W    = (const float*)d_in[7];
    float* out = (float*)d_out;

    const int* row = ei;
    const int* col = ei + EE;

    cudaFuncSetAttribute(mma_gemm_kernel, cudaFuncAttributeMaxDynamicSharedMemorySize,
                         SMEM_GEMM_TOTAL);

    zero_counts_kernel<<<(NN + 255) / 256, 256>>>();       // 0
    count_kernel<<<(EE + 255) / 256, 256>>>(col);          // 1
    scan_kernel<<<1, 1024>>>();                            // 2
    row_embed_kernel<<<NN, 256>>>(init, w1, b1, w2, b2);   // 3  <- ncu capture slot
    scatter_kernel<<<(EE + 255) / 256, 256>>>(row, col, attr);   // 4
    transpose_w_kernel<<<64, 256>>>(W);                    // 5

    dim3 gemm_grid(DD / 128, M_PAD / 128);
    for (int layer = 0; layer < 3; layer++) {
        mma_gemm_kernel<<<gemm_grid, 256, SMEM_GEMM_TOTAL>>>();
        agg_kernel<<<NN, 256>>>(layer == 2 ? out : nullptr);
    }
}